// round 4
// baseline (speedup 1.0000x reference)
#include <cuda_runtime.h>

// InvConditionalLinear forward: per-pixel 32x32 solve W z = x, sum log|det W|.
// B=16, C=32, H=W=48 (HW=2304). 16 lanes per matrix (2 matrices per warp),
// lane owns rows hl and hl+16 as f32x2 pairs. Width-16 shfl broadcasts serve
// both matrices per instruction. Pivot reciprocal is precomputed by the next
// owner one iteration early and smuggled in the dead lane of the pivot block.

#define FULL_MASK 0xffffffffu

static constexpr int B = 16, C = 32, HW = 48 * 48;     // 2304
static constexpr int PIX = 8;                          // pixels per block (128 thr)
static constexpr int RSTR = 36;                        // row stride (floats), 16B-aligned rows
static constexpr int MSTR = 32 * RSTR;                 // 1152 floats per pixel
static constexpr int BLOCKS_PER_BATCH = HW / PIX;      // 288

static __device__ float g_pixlogdet[B * HW];
static __device__ int   g_done[B];                     // zero-init; reset by finisher

__device__ __forceinline__ unsigned long long pack2(float x, float y) {
    unsigned long long r;
    asm("mov.b64 %0, {%1, %2};" : "=l"(r) : "r"(__float_as_uint(x)), "r"(__float_as_uint(y)));
    return r;
}
__device__ __forceinline__ float lo32(unsigned long long v) { return __uint_as_float((unsigned)v); }
__device__ __forceinline__ float hi32(unsigned long long v) { return __uint_as_float((unsigned)(v >> 32)); }
__device__ __forceinline__ unsigned long long ffma2(unsigned long long a, unsigned long long b,
                                                    unsigned long long c) {
    unsigned long long d;
    asm("fma.rn.f32x2 %0, %1, %2, %3;" : "=l"(d) : "l"(a), "l"(b), "l"(c));
    return d;
}

__global__ __launch_bounds__(128, 5) void gj_solve_kernel(
    const float* __restrict__ input,     // [B, C, H, W]
    const float* __restrict__ weight,    // [B, C*C, H, W]
    const float* __restrict__ logdet_in, // [B]
    float* __restrict__ out)             // z [B,C,H,W] then logdet [B]
{
    __shared__ float s_w[PIX * MSTR];    // 36 KB
    __shared__ float s_x[PIX * 32];
    __shared__ float s_z[PIX * 32];
    __shared__ float s_red[128];
    __shared__ int   s_last;

    const int t    = threadIdx.x;
    const int lane = t & 31;
    const int w    = t >> 5;
    const int q0   = blockIdx.x * PIX;
    const int b    = q0 / HW;
    const int qm0  = q0 - b * HW;

    // ---- Phase 1: coalesced global load, stage to smem (transpose to row-major) ----
    const float* wbase = weight + (size_t)b * (size_t)(C * C) * HW + qm0;
    #pragma unroll
    for (int it = 0; it < 16; ++it) {
        int idx = it * 128 + t;                  // 0..2047
        int c   = idx >> 1;                      // channel 0..1023
        int pp  = (idx & 1) << 2;                // pixel 0 or 4
        float4 v = *reinterpret_cast<const float4*>(wbase + (size_t)c * HW + pp);
        int sb = (c >> 5) * RSTR + (c & 31);     // row = c>>5, col = c&31
        s_w[(pp + 0) * MSTR + sb] = v.x;
        s_w[(pp + 1) * MSTR + sb] = v.y;
        s_w[(pp + 2) * MSTR + sb] = v.z;
        s_w[(pp + 3) * MSTR + sb] = v.w;
    }
    #pragma unroll
    for (int it = 0; it < 2; ++it) {
        int c = it * 16 + (t >> 3), pp = t & 7;
        s_x[pp * 32 + c] = input[(size_t)b * C * HW + (size_t)c * HW + qm0 + pp];
    }
    __syncthreads();

    // ---- Phase 2: Gauss-Jordan; lanes 0-15 = matrix(2w), lanes 16-31 = matrix(2w+1) ----
    const int hl  = lane & 15;
    const int pix = 2 * w + (lane >> 4);

    unsigned long long a2[16], b2[16];           // rows hl and hl+16, 16 f32x2 each
    {
        const float* rA = s_w + pix * MSTR + hl * RSTR;
        const float* rB = s_w + pix * MSTR + (hl + 16) * RSTR;
        #pragma unroll
        for (int q = 0; q < 8; ++q) {
            float4 va = *reinterpret_cast<const float4*>(rA + 4 * q);
            float4 vb = *reinterpret_cast<const float4*>(rB + 4 * q);
            a2[2 * q] = pack2(va.x, va.y); a2[2 * q + 1] = pack2(va.z, va.w);
            b2[2 * q] = pack2(vb.x, vb.y); b2[2 * q + 1] = pack2(vb.z, vb.w);
        }
    }
    float rhsA = s_x[pix * 32 + hl];
    float rhsB = s_x[pix * 32 + hl + 16];

    float pivA = 1.0f, pivB = 1.0f, pinvA = 1.0f, pinvB = 1.0f;
    float pinv_own;                              // owner lane: 1/pivot for current k
    {
        const float e0 = lo32(a2[0]);
        const float p0 = __fdividef(1.0f, e0);
        pinv_own = p0;
        if (hl == 0) { pivA = e0; pinvA = p0; }
    }

    #pragma unroll
    for (int k = 0; k < 32; ++k) {
        const int  ip  = k >> 1;
        const int  ow  = k & 15;
        const bool inA = (k < 16);               // pivot row lives in a2 or b2

        float pinv;
        unsigned long long pb = 0;
        if ((k & 1) == 0) {
            // smuggle pinv in the dead lo element (col k dies this iteration)
            unsigned long long src = inA ? a2[ip] : b2[ip];
            unsigned long long ts  = pack2(pinv_own, hi32(src));
            pb   = __shfl_sync(FULL_MASK, ts, ow, 16);
            pinv = lo32(pb);
        } else {
            pinv = __shfl_sync(FULL_MASK, pinv_own, ow, 16);
        }

        const float eA = (k & 1) ? hi32(a2[ip]) : lo32(a2[ip]);
        const float eB = (k & 1) ? hi32(b2[ip]) : lo32(b2[ip]);
        float mA = eA * pinv;
        float mB = eB * pinv;
        if (inA  && hl == ow) mA = 0.0f;         // pivot row not eliminated
        if (!inA && hl == ow) mB = 0.0f;

        const unsigned long long nmA = pack2(-mA, -mA);
        const unsigned long long nmB = pack2(-mB, -mB);

        const int start = (k & 1) ? ip + 1 : ip; // odd k: block ip fully dead after
        #pragma unroll
        for (int i = start; i < 16; ++i) {
            unsigned long long pr = (((k & 1) == 0) && i == ip)
                ? pb
                : __shfl_sync(FULL_MASK, inA ? a2[i] : b2[i], ow, 16);
            a2[i] = ffma2(nmA, pr, a2[i]);
            b2[i] = ffma2(nmB, pr, b2[i]);
        }

        const float rk = __shfl_sync(FULL_MASK, inA ? rhsA : rhsB, ow, 16);
        rhsA = fmaf(-mA, rk, rhsA);
        rhsB = fmaf(-mB, rk, rhsB);

        // prefetch next pivot's reciprocal in its owner lane (element is final now)
        if (k < 31) {
            const int  kn  = k + 1;
            const int  ipn = kn >> 1;
            const int  own = kn & 15;
            unsigned long long blk = (kn < 16) ? a2[ipn] : b2[ipn];
            const float elem = (kn & 1) ? hi32(blk) : lo32(blk);
            const float pn   = __fdividef(1.0f, elem);
            if (hl == own) {
                pinv_own = pn;
                if (kn < 16) { pivA = elem; pinvA = pn; }
                else         { pivB = elem; pinvB = pn; }
            }
        }
    }

    const float zA = rhsA * pinvA;
    const float zB = rhsB * pinvB;

    // per-matrix log|det| = sum over 16 lanes of log|pivots owned| (2 each)
    float s = __logf(fabsf(pivA)) + __logf(fabsf(pivB));
    #pragma unroll
    for (int off = 8; off; off >>= 1) s += __shfl_xor_sync(FULL_MASK, s, off, 16);
    if (hl == 0) g_pixlogdet[q0 + pix] = s;

    s_z[pix * 32 + hl]      = zA;
    s_z[pix * 32 + hl + 16] = zB;
    __syncthreads();

    // ---- Phase 3: coalesced store of z ----
    #pragma unroll
    for (int it = 0; it < 2; ++it) {
        int c = it * 16 + (t >> 3), pp = t & 7;
        out[(size_t)b * C * HW + (size_t)c * HW + qm0 + pp] = s_z[pp * 32 + c];
    }

    // ---- Phase 4: last block per batch reduces the 2304 pixel logdets ----
    __threadfence();
    if (t == 0) {
        int v = atomicAdd(&g_done[b], 1);
        s_last = (v == BLOCKS_PER_BATCH - 1);
    }
    __syncthreads();
    if (s_last) {
        __threadfence();
        float acc = 0.0f;
        #pragma unroll
        for (int r = 0; r < 18; ++r)                 // 2304 = 18 * 128, fixed order
            acc += g_pixlogdet[b * HW + r * 128 + t];
        s_red[t] = acc;
        __syncthreads();
        #pragma unroll
        for (int off = 64; off; off >>= 1) {
            if (t < off) s_red[t] += s_red[t + off];
            __syncthreads();
        }
        if (t == 0) {
            out[(size_t)B * C * HW + b] = logdet_in[b] - s_red[0];
            g_done[b] = 0;                           // reset for next graph replay
        }
    }
}

extern "C" void kernel_launch(void* const* d_in, const int* in_sizes, int n_in,
                              void* d_out, int out_size)
{
    const float* input  = (const float*)d_in[0];
    const float* weight = (const float*)d_in[1];
    const float* logdet = (const float*)d_in[2];
    float* out = (float*)d_out;

    gj_solve_kernel<<<(B * HW) / PIX, 128>>>(input, weight, logdet, out);
}

// round 5
// speedup vs baseline: 1.1898x; 1.1898x over previous
#include <cuda_runtime.h>

// InvConditionalLinear forward: per-pixel 32x32 solve W z = x, sum log|det W|.
// B=16, C=32, H=W=48 (HW=2304). 16 lanes per matrix (2 matrices per warp),
// lane owns rows hl and hl+16 as f32x2 pairs. Pivot-row broadcast through a
// per-warp double-buffered smem row (owner STS.128, lanes LDS.128 broadcast,
// 16B per instruction vs 4B for SHFL). Owner pre-replaces the pivot element
// with its reciprocal so no MUFU sits on the receive path. Unpivoted GJ.

#define FULL_MASK 0xffffffffu

static constexpr int B = 16, C = 32, HW = 48 * 48;     // 2304
static constexpr int PIX = 8;                          // pixels per block (128 thr)
static constexpr int RSTR = 36;                        // row stride (floats)
static constexpr int MSTR = 32 * RSTR;                 // 1152 floats per pixel
static constexpr int BLOCKS_PER_BATCH = HW / PIX;      // 288
static constexpr int WROW = 144;                       // row-buffer floats per warp

static __device__ float g_pixlogdet[B * HW];
static __device__ int   g_done[B];

__device__ __forceinline__ unsigned long long pack2(float x, float y) {
    unsigned long long r;
    asm("mov.b64 %0, {%1, %2};" : "=l"(r) : "r"(__float_as_uint(x)), "r"(__float_as_uint(y)));
    return r;
}
__device__ __forceinline__ float lo32(unsigned long long v) { return __uint_as_float((unsigned)v); }
__device__ __forceinline__ float hi32(unsigned long long v) { return __uint_as_float((unsigned)(v >> 32)); }
__device__ __forceinline__ unsigned long long ffma2(unsigned long long a, unsigned long long b,
                                                    unsigned long long c) {
    unsigned long long d;
    asm("fma.rn.f32x2 %0, %1, %2, %3;" : "=l"(d) : "l"(a), "l"(b), "l"(c));
    return d;
}

__global__ __launch_bounds__(128) void gj_solve_kernel(
    const float* __restrict__ input,     // [B, C, H, W]
    const float* __restrict__ weight,    // [B, C*C, H, W]
    const float* __restrict__ logdet_in, // [B]
    float* __restrict__ out)             // z [B,C,H,W] then logdet [B]
{
    __shared__ float s_w[PIX * MSTR];                  // 36 KB
    __shared__ float s_x[PIX * 32];
    __shared__ float s_z[PIX * 32];
    __shared__ __align__(16) float s_row[4 * WROW];    // per-warp double-buffered rows
    __shared__ float s_red[128];
    __shared__ int   s_last;

    const int t    = threadIdx.x;
    const int lane = t & 31;
    const int w    = t >> 5;
    const int q0   = blockIdx.x * PIX;
    const int b    = q0 / HW;
    const int qm0  = q0 - b * HW;

    // ---- Phase 1: coalesced global load, stage to smem (transpose to row-major) ----
    const float* wbase = weight + (size_t)b * (size_t)(C * C) * HW + qm0;
    #pragma unroll
    for (int it = 0; it < 16; ++it) {
        int idx = it * 128 + t;
        int c   = idx >> 1;
        int pp  = (idx & 1) << 2;
        float4 v = *reinterpret_cast<const float4*>(wbase + (size_t)c * HW + pp);
        int sb = (c >> 5) * RSTR + (c & 31);
        s_w[(pp + 0) * MSTR + sb] = v.x;
        s_w[(pp + 1) * MSTR + sb] = v.y;
        s_w[(pp + 2) * MSTR + sb] = v.z;
        s_w[(pp + 3) * MSTR + sb] = v.w;
    }
    #pragma unroll
    for (int it = 0; it < 2; ++it) {
        int c = it * 16 + (t >> 3), pp = t & 7;
        s_x[pp * 32 + c] = input[(size_t)b * C * HW + (size_t)c * HW + qm0 + pp];
    }
    __syncthreads();

    // ---- Phase 2: Gauss-Jordan; lanes 0-15 = matrix(2w), lanes 16-31 = matrix(2w+1) ----
    const int hl  = lane & 15;
    const int pix = 2 * w + (lane >> 4);

    unsigned long long a2[16], b2[16];                 // rows hl and hl+16
    {
        const float* rA = s_w + pix * MSTR + hl * RSTR;
        const float* rB = s_w + pix * MSTR + (hl + 16) * RSTR;
        #pragma unroll
        for (int q = 0; q < 8; ++q) {
            float4 va = *reinterpret_cast<const float4*>(rA + 4 * q);
            float4 vb = *reinterpret_cast<const float4*>(rB + 4 * q);
            a2[2 * q] = pack2(va.x, va.y); a2[2 * q + 1] = pack2(va.z, va.w);
            b2[2 * q] = pack2(vb.x, vb.y); b2[2 * q + 1] = pack2(vb.z, vb.w);
        }
    }
    float rhsA = s_x[pix * 32 + hl];
    float rhsB = s_x[pix * 32 + hl + 16];

    float pivA = 1.0f, pivB = 1.0f, pinvA = 1.0f, pinvB = 1.0f;

    // Per-warp row buffer; A half at +0, B half at +36 floats (4-bank offset:
    // the two 16B broadcasts of each LDS.128 hit disjoint banks).
    float* rbase = s_row + w * WROW + ((lane & 16) ? 36 : 0);

    #pragma unroll
    for (int k = 0; k < 32; ++k) {
        const int  j0  = k >> 2;                       // first live float4 (pivot block)
        const int  ip  = k >> 1;                       // ull index holding pivot
        const int  ow  = k & 15;
        const bool inA = (k < 16);
        float* rb = rbase + (k & 1) * 72;              // double buffer

        // ---- owner publishes its pivot row, pivot element replaced by 1/piv ----
        if (hl == ow) {
            float piv, pinv;
            if (inA) {
                piv  = (k & 1) ? hi32(a2[ip]) : lo32(a2[ip]);
                pinv = __fdividef(1.0f, piv);
                pivA = piv; pinvA = pinv;
                unsigned long long vm = (k & 1) ? pack2(lo32(a2[ip]), pinv)
                                                : pack2(pinv, hi32(a2[ip]));
                #pragma unroll
                for (int j = j0; j < 8; ++j) {
                    ulonglong2 v;
                    v.x = (2 * j     == ip) ? vm : a2[2 * j];
                    v.y = (2 * j + 1 == ip) ? vm : a2[2 * j + 1];
                    *reinterpret_cast<ulonglong2*>(rb + 4 * j) = v;
                }
            } else {
                piv  = (k & 1) ? hi32(b2[ip]) : lo32(b2[ip]);
                pinv = __fdividef(1.0f, piv);
                pivB = piv; pinvB = pinv;
                unsigned long long vm = (k & 1) ? pack2(lo32(b2[ip]), pinv)
                                                : pack2(pinv, hi32(b2[ip]));
                #pragma unroll
                for (int j = j0; j < 8; ++j) {
                    ulonglong2 v;
                    v.x = (2 * j     == ip) ? vm : b2[2 * j];
                    v.y = (2 * j + 1 == ip) ? vm : b2[2 * j + 1];
                    *reinterpret_cast<ulonglong2*>(rb + 4 * j) = v;
                }
            }
        }
        __syncwarp();

        // ---- all lanes: read pivot block, derive multipliers ----
        ulonglong2 pb = *reinterpret_cast<const ulonglong2*>(rb + 4 * j0);
        const unsigned long long pu = (ip & 1) ? pb.y : pb.x;
        const float pinv = (k & 1) ? hi32(pu) : lo32(pu);

        const float eA = (k & 1) ? hi32(a2[ip]) : lo32(a2[ip]);
        const float eB = (k & 1) ? hi32(b2[ip]) : lo32(b2[ip]);
        float mA = eA * pinv;
        float mB = eB * pinv;
        if (inA  && hl == ow) mA = 0.0f;
        if (!inA && hl == ow) mB = 0.0f;

        const unsigned long long nmA = pack2(-mA, -mA);
        const unsigned long long nmB = pack2(-mB, -mB);

        // ---- update live blocks (pinv-laced garbage lands only in dead cols) ----
        #pragma unroll
        for (int j = j0; j < 8; ++j) {
            ulonglong2 v = (j == j0)
                ? pb
                : *reinterpret_cast<const ulonglong2*>(rb + 4 * j);
            a2[2 * j]     = ffma2(nmA, v.x, a2[2 * j]);
            a2[2 * j + 1] = ffma2(nmA, v.y, a2[2 * j + 1]);
            b2[2 * j]     = ffma2(nmB, v.x, b2[2 * j]);
            b2[2 * j + 1] = ffma2(nmB, v.y, b2[2 * j + 1]);
        }

        const float rk = __shfl_sync(FULL_MASK, inA ? rhsA : rhsB, ow, 16);
        rhsA = fmaf(-mA, rk, rhsA);
        rhsB = fmaf(-mB, rk, rhsB);
    }

    const float zA = rhsA * pinvA;
    const float zB = rhsB * pinvB;

    // per-matrix log|det| = sum over 16 lanes of log|pivots owned| (2 each)
    float s = __logf(fabsf(pivA)) + __logf(fabsf(pivB));
    #pragma unroll
    for (int off = 8; off; off >>= 1) s += __shfl_xor_sync(FULL_MASK, s, off, 16);
    if (hl == 0) g_pixlogdet[q0 + pix] = s;

    s_z[pix * 32 + hl]      = zA;
    s_z[pix * 32 + hl + 16] = zB;
    __syncthreads();

    // ---- Phase 3: coalesced store of z ----
    #pragma unroll
    for (int it = 0; it < 2; ++it) {
        int c = it * 16 + (t >> 3), pp = t & 7;
        out[(size_t)b * C * HW + (size_t)c * HW + qm0 + pp] = s_z[pp * 32 + c];
    }

    // ---- Phase 4: last block per batch reduces the 2304 pixel logdets ----
    __threadfence();
    if (t == 0) {
        int v = atomicAdd(&g_done[b], 1);
        s_last = (v == BLOCKS_PER_BATCH - 1);
    }
    __syncthreads();
    if (s_last) {
        __threadfence();
        float acc = 0.0f;
        #pragma unroll
        for (int r = 0; r < 18; ++r)                 // 2304 = 18 * 128, fixed order
            acc += g_pixlogdet[b * HW + r * 128 + t];
        s_red[t] = acc;
        __syncthreads();
        #pragma unroll
        for (int off = 64; off; off >>= 1) {
            if (t < off) s_red[t] += s_red[t + off];
            __syncthreads();
        }
        if (t == 0) {
            out[(size_t)B * C * HW + b] = logdet_in[b] - s_red[0];
            g_done[b] = 0;                           // reset for next graph replay
        }
    }
}

extern "C" void kernel_launch(void* const* d_in, const int* in_sizes, int n_in,
                              void* d_out, int out_size)
{
    const float* input  = (const float*)d_in[0];
    const float* weight = (const float*)d_in[1];
    const float* logdet = (const float*)d_in[2];
    float* out = (float*)d_out;

    gj_solve_kernel<<<(B * HW) / PIX, 128>>>(input, weight, logdet, out);
}

// round 6
// speedup vs baseline: 1.4070x; 1.1825x over previous
#include <cuda_runtime.h>

// InvConditionalLinear forward: per-pixel 32x32 solve W z = x, sum log|det W|.
// B=16, C=32, H=W=48 (HW=2304). 2 matrices per warp x 2 column-parity slices:
// four 8-lane subgroups; subgroup = (matrix, parity). Lane owns 4 rows
// (sg, sg+8, sg+16, sg+24) x 8 f32x2 blocks of its parity. Width-8 shfl
// broadcasts pivot-row data for all 4 subgroups in one instruction.
// Multiplier column is exchanged between parity siblings via shfl_xor(8).
// Unpivoted Gauss-Jordan (W = I + 0.1*N is well conditioned).

#define FULL_MASK 0xffffffffu

static constexpr int B = 16, C = 32, HW = 48 * 48;     // 2304
static constexpr int PIX = 8;                          // pixels per block (128 thr)
static constexpr int RSTR = 36;                        // row stride (floats)
static constexpr int MSTR = 32 * RSTR;                 // 1152 floats per pixel
static constexpr int BLOCKS_PER_BATCH = HW / PIX;      // 288

static __device__ float g_pixlogdet[B * HW];
static __device__ int   g_done[B];

__device__ __forceinline__ unsigned long long pack2(float x, float y) {
    unsigned long long r;
    asm("mov.b64 %0, {%1, %2};" : "=l"(r) : "r"(__float_as_uint(x)), "r"(__float_as_uint(y)));
    return r;
}
__device__ __forceinline__ float lo32(unsigned long long v) { return __uint_as_float((unsigned)v); }
__device__ __forceinline__ float hi32(unsigned long long v) { return __uint_as_float((unsigned)(v >> 32)); }
__device__ __forceinline__ unsigned long long ffma2(unsigned long long a, unsigned long long b,
                                                    unsigned long long c) {
    unsigned long long d;
    asm("fma.rn.f32x2 %0, %1, %2, %3;" : "=l"(d) : "l"(a), "l"(b), "l"(c));
    return d;
}

__global__ __launch_bounds__(128) void gj_solve_kernel(
    const float* __restrict__ input,     // [B, C, H, W]
    const float* __restrict__ weight,    // [B, C*C, H, W]
    const float* __restrict__ logdet_in, // [B]
    float* __restrict__ out)             // z [B,C,H,W] then logdet [B]
{
    __shared__ float s_w[PIX * MSTR];    // 36 KB
    __shared__ float s_x[PIX * 32];
    __shared__ float s_z[PIX * 32];
    __shared__ float s_red[128];
    __shared__ int   s_last;

    const int t    = threadIdx.x;
    const int lane = t & 31;
    const int w    = t >> 5;
    const int q0   = blockIdx.x * PIX;
    const int b    = q0 / HW;
    const int qm0  = q0 - b * HW;

    // ---- Phase 1: coalesced global load, stage to smem (transpose to row-major) ----
    const float* wbase = weight + (size_t)b * (size_t)(C * C) * HW + qm0;
    #pragma unroll
    for (int it = 0; it < 16; ++it) {
        int idx = it * 128 + t;
        int c   = idx >> 1;
        int pp  = (idx & 1) << 2;
        float4 v = *reinterpret_cast<const float4*>(wbase + (size_t)c * HW + pp);
        int sb = (c >> 5) * RSTR + (c & 31);
        s_w[(pp + 0) * MSTR + sb] = v.x;
        s_w[(pp + 1) * MSTR + sb] = v.y;
        s_w[(pp + 2) * MSTR + sb] = v.z;
        s_w[(pp + 3) * MSTR + sb] = v.w;
    }
    #pragma unroll
    for (int it = 0; it < 2; ++it) {
        int c = it * 16 + (t >> 3), pp = t & 7;
        s_x[pp * 32 + c] = input[(size_t)b * C * HW + (size_t)c * HW + qm0 + pp];
    }
    __syncthreads();

    // ---- Phase 2: Gauss-Jordan ----
    // Subgroup layout: mat = lane>>4, par = (lane>>3)&1, sg = lane&7.
    // Lane owns rows sg+8t (t=0..3), f32x2 blocks 2s+par (s=0..7) of matrix mat.
    const int mat = lane >> 4;
    const int par = (lane >> 3) & 1;
    const int sg  = lane & 7;
    const int pix = 2 * w + mat;

    unsigned long long d[4][8];
    {
        const float* rbase = s_w + pix * MSTR + 2 * par;
        #pragma unroll
        for (int tt = 0; tt < 4; ++tt) {
            const float* rp = rbase + (sg + 8 * tt) * RSTR;
            #pragma unroll
            for (int s = 0; s < 8; ++s)
                d[tt][s] = *reinterpret_cast<const unsigned long long*>(rp + 4 * s);
        }
    }
    float rhs[4];
    #pragma unroll
    for (int tt = 0; tt < 4; ++tt)
        rhs[tt] = s_x[pix * 32 + sg + 8 * tt];

    float psave[4]  = {1.0f, 1.0f, 1.0f, 1.0f};
    float pisave[4] = {1.0f, 1.0f, 1.0f, 1.0f};

    #pragma unroll
    for (int k = 0; k < 32; ++k) {
        const int s0 = k >> 2;                 // first live slot (float4 trim)
        const int ow = k & 7;                  // owner lane within each subgroup
        const int tk = k >> 3;                 // owner's local row index
        const int pk = (k >> 1) & 1;           // parity group holding column k

        // broadcast pivot row k: each 8-lane subgroup sources its own slice
        unsigned long long u[8];
        #pragma unroll
        for (int s = s0; s < 8; ++s)
            u[s] = __shfl_sync(FULL_MASK, d[tk][s], ow, 8);

        // pivot element lives in block k>>1 = slot s0 of parity pk
        const float pe   = (k & 1) ? hi32(u[s0]) : lo32(u[s0]);
        const float pinv = __fdividef(1.0f, pe);

        // parity-pk lanes compute multipliers for their 4 rows (others: garbage)
        float mv[4];
        #pragma unroll
        for (int tt = 0; tt < 4; ++tt)
            mv[tt] = ((k & 1) ? hi32(d[tt][s0]) : lo32(d[tt][s0])) * pinv;
        const bool own = (sg == ow) && (par == pk);
        if (own) {
            mv[tk]     = 0.0f;                 // pivot row is not eliminated
            psave[tk]  = pe;                   // capture pivot + reciprocal
            pisave[tk] = pinv;
        }

        // exchange multipliers with parity sibling (lane ^ 8), branch-free
        unsigned long long mm01 = pack2(mv[0], mv[1]);
        unsigned long long mm23 = pack2(mv[2], mv[3]);
        const unsigned long long e01 = __shfl_xor_sync(FULL_MASK, mm01, 8);
        const unsigned long long e23 = __shfl_xor_sync(FULL_MASK, mm23, 8);
        if (par != pk) { mm01 = e01; mm23 = e23; }
        mv[0] = lo32(mm01); mv[1] = hi32(mm01);
        mv[2] = lo32(mm23); mv[3] = hi32(mm23);

        const unsigned long long nm0 = pack2(-mv[0], -mv[0]);
        const unsigned long long nm1 = pack2(-mv[1], -mv[1]);
        const unsigned long long nm2 = pack2(-mv[2], -mv[2]);
        const unsigned long long nm3 = pack2(-mv[3], -mv[3]);

        #pragma unroll
        for (int s = s0; s < 8; ++s) {
            d[0][s] = ffma2(nm0, u[s], d[0][s]);
            d[1][s] = ffma2(nm1, u[s], d[1][s]);
            d[2][s] = ffma2(nm2, u[s], d[2][s]);
            d[3][s] = ffma2(nm3, u[s], d[3][s]);
        }

        const float rk = __shfl_sync(FULL_MASK, rhs[tk], ow, 8);
        rhs[0] = fmaf(-mv[0], rk, rhs[0]);
        rhs[1] = fmaf(-mv[1], rk, rhs[1]);
        rhs[2] = fmaf(-mv[2], rk, rhs[2]);
        rhs[3] = fmaf(-mv[3], rk, rhs[3]);
    }

    // The lane with par == bit1(sg) captured all 4 pivots of its rows
    // (rows sg+8t all have bit1(row) = bit1(sg)); others kept psave = 1 -> log 0.
    const bool match = (((sg >> 1) & 1) == par);

    float la = __logf(fabsf(psave[0])) + __logf(fabsf(psave[1]))
             + __logf(fabsf(psave[2])) + __logf(fabsf(psave[3]));
    #pragma unroll
    for (int off = 8; off; off >>= 1) la += __shfl_xor_sync(FULL_MASK, la, off, 16);
    if ((lane & 15) == 0) g_pixlogdet[q0 + pix] = la;

    if (match) {
        #pragma unroll
        for (int tt = 0; tt < 4; ++tt)
            s_z[pix * 32 + sg + 8 * tt] = rhs[tt] * pisave[tt];
    }
    __syncthreads();

    // ---- Phase 3: coalesced store of z ----
    #pragma unroll
    for (int it = 0; it < 2; ++it) {
        int c = it * 16 + (t >> 3), pp = t & 7;
        out[(size_t)b * C * HW + (size_t)c * HW + qm0 + pp] = s_z[pp * 32 + c];
    }

    // ---- Phase 4: last block per batch reduces the 2304 pixel logdets ----
    __threadfence();
    if (t == 0) {
        int v = atomicAdd(&g_done[b], 1);
        s_last = (v == BLOCKS_PER_BATCH - 1);
    }
    __syncthreads();
    if (s_last) {
        __threadfence();
        float acc = 0.0f;
        #pragma unroll
        for (int r = 0; r < 18; ++r)                 // 2304 = 18 * 128, fixed order
            acc += g_pixlogdet[b * HW + r * 128 + t];
        s_red[t] = acc;
        __syncthreads();
        #pragma unroll
        for (int off = 64; off; off >>= 1) {
            if (t < off) s_red[t] += s_red[t + off];
            __syncthreads();
        }
        if (t == 0) {
            out[(size_t)B * C * HW + b] = logdet_in[b] - s_red[0];
            g_done[b] = 0;                           // reset for next graph replay
        }
    }
}

extern "C" void kernel_launch(void* const* d_in, const int* in_sizes, int n_in,
                              void* d_out, int out_size)
{
    const float* input  = (const float*)d_in[0];
    const float* weight = (const float*)d_in[1];
    const float* logdet = (const float*)d_in[2];
    float* out = (float*)d_out;

    gj_solve_kernel<<<(B * HW) / PIX, 128>>>(input, weight, logdet, out);
}

// round 7
// speedup vs baseline: 1.4729x; 1.0469x over previous
#include <cuda_runtime.h>

// InvConditionalLinear forward: per-pixel 32x32 solve W z = x, sum log|det W|.
// B=16, C=32, H=W=48 (HW=2304). 2 matrices per warp x 2 column-parity slices
// (four 8-lane subgroups). Lane owns 4 rows x 8 f32x2 blocks of its parity.
// Software-pipelined: multipliers/pivot-reciprocal/exchange for iteration k+1
// are computed at the tail of iteration k (column k+1 is final once slot sn is
// updated), so each iteration's head is only the width-8 row broadcast + FFMA2.

#define FULL_MASK 0xffffffffu

static constexpr int B = 16, C = 32, HW = 48 * 48;     // 2304
static constexpr int PIX = 8;                          // pixels per block (128 thr)
static constexpr int RSTR = 36;                        // row stride (floats)
static constexpr int MSTR = 1156;                      // pixel stride: !=0 mod 8 banks
static constexpr int BLOCKS_PER_BATCH = HW / PIX;      // 288

static __device__ float g_pixlogdet[B * HW];
static __device__ int   g_done[B];

__device__ __forceinline__ unsigned long long pack2(float x, float y) {
    unsigned long long r;
    asm("mov.b64 %0, {%1, %2};" : "=l"(r) : "r"(__float_as_uint(x)), "r"(__float_as_uint(y)));
    return r;
}
__device__ __forceinline__ float lo32(unsigned long long v) { return __uint_as_float((unsigned)v); }
__device__ __forceinline__ float hi32(unsigned long long v) { return __uint_as_float((unsigned)(v >> 32)); }
__device__ __forceinline__ unsigned long long ffma2(unsigned long long a, unsigned long long b,
                                                    unsigned long long c) {
    unsigned long long d;
    asm("fma.rn.f32x2 %0, %1, %2, %3;" : "=l"(d) : "l"(a), "l"(b), "l"(c));
    return d;
}

__global__ __launch_bounds__(128) void gj_solve_kernel(
    const float* __restrict__ input,     // [B, C, H, W]
    const float* __restrict__ weight,    // [B, C*C, H, W]
    const float* __restrict__ logdet_in, // [B]
    float* __restrict__ out)             // z [B,C,H,W] then logdet [B]
{
    __shared__ float s_w[PIX * MSTR];    // ~37 KB
    __shared__ float s_x[PIX * 32];
    __shared__ float s_z[PIX * 32];
    __shared__ float s_red[128];
    __shared__ int   s_last;

    const int t    = threadIdx.x;
    const int lane = t & 31;
    const int w    = t >> 5;
    const int q0   = blockIdx.x * PIX;
    const int b    = q0 / HW;
    const int qm0  = q0 - b * HW;

    // ---- Phase 1: coalesced global load, stage to smem (transpose to row-major) ----
    const float* wbase = weight + (size_t)b * (size_t)(C * C) * HW + qm0;
    #pragma unroll
    for (int it = 0; it < 16; ++it) {
        int idx = it * 128 + t;
        int c   = idx >> 1;
        int pp  = (idx & 1) << 2;
        float4 v = *reinterpret_cast<const float4*>(wbase + (size_t)c * HW + pp);
        int sb = (c >> 5) * RSTR + (c & 31);
        s_w[(pp + 0) * MSTR + sb] = v.x;
        s_w[(pp + 1) * MSTR + sb] = v.y;
        s_w[(pp + 2) * MSTR + sb] = v.z;
        s_w[(pp + 3) * MSTR + sb] = v.w;
    }
    #pragma unroll
    for (int it = 0; it < 2; ++it) {
        int c = it * 16 + (t >> 3), pp = t & 7;
        s_x[pp * 32 + c] = input[(size_t)b * C * HW + (size_t)c * HW + qm0 + pp];
    }
    __syncthreads();

    // ---- Phase 2: Gauss-Jordan ----
    // mat = lane>>4, par = (lane>>3)&1, sg = lane&7.
    // Lane owns rows sg+8t (t=0..3), f32x2 blocks 2s+par (s=0..7) of matrix mat.
    const int mat = lane >> 4;
    const int par = (lane >> 3) & 1;
    const int sg  = lane & 7;
    const int pix = 2 * w + mat;

    unsigned long long d[4][8];
    {
        const float* rb = s_w + pix * MSTR + 2 * par;
        #pragma unroll
        for (int tt = 0; tt < 4; ++tt) {
            const float* rp = rb + (sg + 8 * tt) * RSTR;
            #pragma unroll
            for (int s = 0; s < 8; ++s)
                d[tt][s] = *reinterpret_cast<const unsigned long long*>(rp + 4 * s);
        }
    }
    float rhs[4];
    #pragma unroll
    for (int tt = 0; tt < 4; ++tt)
        rhs[tt] = s_x[pix * 32 + sg + 8 * tt];

    float psave[4]  = {1.0f, 1.0f, 1.0f, 1.0f};
    float pisave[4] = {1.0f, 1.0f, 1.0f, 1.0f};

    // ---- pipeline prologue: multipliers for k=0 (column 0 is original data) ----
    unsigned long long nm[4];   // per-row packed negated multipliers for current k
    float rkv;                  // pivot-row rhs for current k
    {
        float e0 = lo32(d[0][0]), e1 = lo32(d[1][0]);
        float e2 = lo32(d[2][0]), e3 = lo32(d[3][0]);
        const float pe = __shfl_sync(FULL_MASK, e0, 0, 16);   // src lane: par=0, sg=0
        const float np = -__fdividef(1.0f, pe);
        float m0 = e0 * np, m1 = e1 * np, m2 = e2 * np, m3 = e3 * np;
        if (sg == 0 && par == 0) { m0 = 0.0f; psave[0] = pe; pisave[0] = -np; }
        const int src = (lane & 16) | sg;                     // parity-0 sibling
        unsigned long long mm01 = __shfl_sync(FULL_MASK, pack2(m0, m1), src, 32);
        unsigned long long mm23 = __shfl_sync(FULL_MASK, pack2(m2, m3), src, 32);
        nm[0] = pack2(lo32(mm01), lo32(mm01));
        nm[1] = pack2(hi32(mm01), hi32(mm01));
        nm[2] = pack2(lo32(mm23), lo32(mm23));
        nm[3] = pack2(hi32(mm23), hi32(mm23));
        rkv = __shfl_sync(FULL_MASK, rhs[0], 0, 8);
    }

    #pragma unroll
    for (int k = 0; k < 32; ++k) {
        const int s0 = k >> 2;                 // first live slot (float4 trim)
        const int ow = k & 7;
        const int tk = k >> 3;
        const int kn = k + 1;
        const int sn = (k < 31) ? (kn >> 2) : s0;   // slot holding column k+1

        // head: broadcast pivot row (serves all four subgroups per instruction)
        unsigned long long u[8];
        #pragma unroll
        for (int s = s0; s < 8; ++s)
            u[s] = __shfl_sync(FULL_MASK, d[tk][s], ow, 8);

        // update next-pivot slot first so the k+1 multiplier chain can start
        #pragma unroll
        for (int tt = 0; tt < 4; ++tt)
            d[tt][sn] = ffma2(nm[tt], u[sn], d[tt][sn]);

        // ---- prefetch multipliers for k+1 (overlaps remaining updates) ----
        unsigned long long nmN[4];
        float rkN = 0.0f;
        if (k < 31) {
            const int pkn = (kn >> 1) & 1;     // parity holding column k+1
            const int own = kn & 7;
            const int tkn = kn >> 3;
            float e[4];
            #pragma unroll
            for (int tt = 0; tt < 4; ++tt)
                e[tt] = (kn & 1) ? hi32(d[tt][sn]) : lo32(d[tt][sn]);
            float etk = (tkn == 0) ? e[0] : (tkn == 1) ? e[1] : (tkn == 2) ? e[2] : e[3];
            const float pe = __shfl_sync(FULL_MASK, etk, pkn * 8 + own, 16);
            const float np = -__fdividef(1.0f, pe);
            float m0 = e[0] * np, m1 = e[1] * np, m2 = e[2] * np, m3 = e[3] * np;
            if (sg == own && par == pkn) {
                if (tkn == 0) m0 = 0.0f; else if (tkn == 1) m1 = 0.0f;
                else if (tkn == 2) m2 = 0.0f; else m3 = 0.0f;
                psave[tkn] = pe; pisave[tkn] = -np;
            }
            const int src = (lane & 16) | (pkn << 3) | sg;
            unsigned long long mm01 = __shfl_sync(FULL_MASK, pack2(m0, m1), src, 32);
            unsigned long long mm23 = __shfl_sync(FULL_MASK, pack2(m2, m3), src, 32);
            nmN[0] = pack2(lo32(mm01), lo32(mm01));
            nmN[1] = pack2(hi32(mm01), hi32(mm01));
            nmN[2] = pack2(lo32(mm23), lo32(mm23));
            nmN[3] = pack2(hi32(mm23), hi32(mm23));
        }

        // remaining block updates + rhs update
        #pragma unroll
        for (int s = s0; s < 8; ++s) {
            if (s == sn) continue;
            d[0][s] = ffma2(nm[0], u[s], d[0][s]);
            d[1][s] = ffma2(nm[1], u[s], d[1][s]);
            d[2][s] = ffma2(nm[2], u[s], d[2][s]);
            d[3][s] = ffma2(nm[3], u[s], d[3][s]);
        }
        rhs[0] = fmaf(lo32(nm[0]), rkv, rhs[0]);
        rhs[1] = fmaf(lo32(nm[1]), rkv, rhs[1]);
        rhs[2] = fmaf(lo32(nm[2]), rkv, rhs[2]);
        rhs[3] = fmaf(lo32(nm[3]), rkv, rhs[3]);

        if (k < 31) {
            rkN = __shfl_sync(FULL_MASK, rhs[kn >> 3], kn & 7, 8);
            nm[0] = nmN[0]; nm[1] = nmN[1]; nm[2] = nmN[2]; nm[3] = nmN[3];
            rkv = rkN;
        }
    }

    // lane with par == bit1(sg) captured all 4 pivots of its rows; others log(1)=0
    const bool match = (((sg >> 1) & 1) == par);

    float la = __logf(fabsf(psave[0])) + __logf(fabsf(psave[1]))
             + __logf(fabsf(psave[2])) + __logf(fabsf(psave[3]));
    #pragma unroll
    for (int off = 8; off; off >>= 1) la += __shfl_xor_sync(FULL_MASK, la, off, 16);
    if ((lane & 15) == 0) g_pixlogdet[q0 + pix] = la;

    if (match) {
        #pragma unroll
        for (int tt = 0; tt < 4; ++tt)
            s_z[pix * 32 + sg + 8 * tt] = rhs[tt] * pisave[tt];
    }
    __syncthreads();

    // ---- Phase 3: coalesced store of z ----
    #pragma unroll
    for (int it = 0; it < 2; ++it) {
        int c = it * 16 + (t >> 3), pp = t & 7;
        out[(size_t)b * C * HW + (size_t)c * HW + qm0 + pp] = s_z[pp * 32 + c];
    }

    // ---- Phase 4: last block per batch reduces the 2304 pixel logdets ----
    __threadfence();
    if (t == 0) {
        int v = atomicAdd(&g_done[b], 1);
        s_last = (v == BLOCKS_PER_BATCH - 1);
    }
    __syncthreads();
    if (s_last) {
        __threadfence();
        float acc = 0.0f;
        #pragma unroll
        for (int r = 0; r < 18; ++r)                 // 2304 = 18 * 128, fixed order
            acc += g_pixlogdet[b * HW + r * 128 + t];
        s_red[t] = acc;
        __syncthreads();
        #pragma unroll
        for (int off = 64; off; off >>= 1) {
            if (t < off) s_red[t] += s_red[t + off];
            __syncthreads();
        }
        if (t == 0) {
            out[(size_t)B * C * HW + b] = logdet_in[b] - s_red[0];
            g_done[b] = 0;                           // reset for next graph replay
        }
    }
}

extern "C" void kernel_launch(void* const* d_in, const int* in_sizes, int n_in,
                              void* d_out, int out_size)
{
    const float* input  = (const float*)d_in[0];
    const float* weight = (const float*)d_in[1];
    const float* logdet = (const float*)d_in[2];
    float* out = (float*)d_out;

    gj_solve_kernel<<<(B * HW) / PIX, 128>>>(input, weight, logdet, out);
}